// round 5
// baseline (speedup 1.0000x reference)
#include <cuda_runtime.h>

#define B_    256
#define T_    250
#define DIN   700
#define H1N   256
#define H2N   256
#define DOUT  20
#define BJ0   0.01f
#define BETA_ 1.8f

// Scratch (device globals — no allocations allowed)
__device__ float g_I1[B_ * T_ * H1N];          // x @ w_i2h1.T  (65.5 MB)
__device__ float g_Wt_i2h1[DIN * H1N];         // [d][j]
__device__ float g_Wt_h12h1[H1N * H1N];        // [k][j]
__device__ float g_Wt_h12h2[H1N * H2N];        // [k][j]
__device__ float g_Wt_h22h2[H2N * H2N];        // [k][j]
__device__ float g_Wt_h2o[H2N * DOUT];         // [k][o]

// ---------------------------------------------------------------------------
// evict_last weight loads (weights are re-read every step; bias L1 retention)
// ---------------------------------------------------------------------------
__device__ __forceinline__ float ldg_el(const float* p) {
    float v;
    asm volatile("ld.global.nc.L1::evict_last.f32 %0, [%1];" : "=f"(v) : "l"(p));
    return v;
}
__device__ __forceinline__ float4 ldg4_el(const float* p) {
    float4 v;
    asm volatile("ld.global.nc.L1::evict_last.v4.f32 {%0,%1,%2,%3}, [%4];"
                 : "=f"(v.x), "=f"(v.y), "=f"(v.z), "=f"(v.w) : "l"(p));
    return v;
}

// ---------------------------------------------------------------------------
// K0: transpose weights to k-major (coalesced spike gathers)
// ---------------------------------------------------------------------------
__global__ void prep_kernel(const float* __restrict__ wi,
                            const float* __restrict__ w11,
                            const float* __restrict__ w12,
                            const float* __restrict__ w22,
                            const float* __restrict__ wo) {
    int idx = blockIdx.x * blockDim.x + threadIdx.x;
    if (idx < H1N * DIN) {
        int r = idx / DIN, c = idx % DIN;
        g_Wt_i2h1[c * H1N + r] = wi[idx];
    }
    if (idx < H1N * H1N) {
        int r = idx / H1N, c = idx % H1N;
        g_Wt_h12h1[c * H1N + r] = w11[idx];
        g_Wt_h12h2[c * H1N + r] = w12[idx];
        g_Wt_h22h2[c * H1N + r] = w22[idx];
    }
    if (idx < DOUT * H2N) {
        int r = idx / H2N, c = idx % H2N;
        g_Wt_h2o[c * DOUT + r] = wo[idx];
    }
}

// ---------------------------------------------------------------------------
// K1: input projection. One CTA per (b,t) sample; gather-sum of active weight
// rows, ascending-d order (bit-exact).
// ---------------------------------------------------------------------------
__global__ __launch_bounds__(256) void input_proj_kernel(const float* __restrict__ x) {
    int row = blockIdx.x;          // b*T + t
    int j   = threadIdx.x;

    __shared__ int lst[DIN];
    __shared__ int nn;

    if (threadIdx.x < 32) {
        int lane = threadIdx.x;
        int cnt = 0;
        const float* xr = x + (size_t)row * DIN;
        for (int base = 0; base < DIN; base += 32) {
            int d = base + lane;
            float v = (d < DIN) ? xr[d] : 0.f;
            unsigned m = __ballot_sync(0xffffffffu, v != 0.f);
            if (v != 0.f)
                lst[cnt + __popc(m & ((1u << lane) - 1u))] = d;
            cnt += __popc(m);
        }
        if (lane == 0) nn = cnt;
    }
    __syncthreads();

    int n = nn;
    float acc = 0.f;
    int i = 0;
    for (; i + 8 <= n; i += 8) {
        float w0 = ldg_el(g_Wt_i2h1 + lst[i]     * H1N + j);
        float w1 = ldg_el(g_Wt_i2h1 + lst[i + 1] * H1N + j);
        float w2 = ldg_el(g_Wt_i2h1 + lst[i + 2] * H1N + j);
        float w3 = ldg_el(g_Wt_i2h1 + lst[i + 3] * H1N + j);
        float w4 = ldg_el(g_Wt_i2h1 + lst[i + 4] * H1N + j);
        float w5 = ldg_el(g_Wt_i2h1 + lst[i + 5] * H1N + j);
        float w6 = ldg_el(g_Wt_i2h1 + lst[i + 6] * H1N + j);
        float w7 = ldg_el(g_Wt_i2h1 + lst[i + 7] * H1N + j);
        acc += w0; acc += w1; acc += w2; acc += w3;
        acc += w4; acc += w5; acc += w6; acc += w7;
    }
    for (; i < n; i++) acc += ldg_el(g_Wt_i2h1 + lst[i] * H1N + j);

    g_I1[(size_t)row * H1N + j] = acc;
}

// ---------------------------------------------------------------------------
// K2 float4 gather: thread covers 4 consecutive neurons (column group c4).
// Accumulation per neuron component is ascending-index — bitwise identical
// to the scalar per-neuron chain. 2-deep pipelined, int4 index loads.
// ---------------------------------------------------------------------------
__device__ __forceinline__ float4 gather4(const int* __restrict__ L,
                                          const int4* __restrict__ L4, int n,
                                          const float* __restrict__ W,
                                          int c4, float4 a) {
    const int nb = n >> 2;
    int i = 0;
    if (nb > 0) {
        int4 idx = L4[0];
        float4 w0 = ldg4_el(W + idx.x * 256 + c4);
        float4 w1 = ldg4_el(W + idx.y * 256 + c4);
        float4 w2 = ldg4_el(W + idx.z * 256 + c4);
        float4 w3 = ldg4_el(W + idx.w * 256 + c4);
        for (int blk = 1; blk < nb; blk++) {
            int4 idn = L4[blk];
            float4 p0 = ldg4_el(W + idn.x * 256 + c4);
            float4 p1 = ldg4_el(W + idn.y * 256 + c4);
            float4 p2 = ldg4_el(W + idn.z * 256 + c4);
            float4 p3 = ldg4_el(W + idn.w * 256 + c4);
            a.x += w0.x; a.y += w0.y; a.z += w0.z; a.w += w0.w;
            a.x += w1.x; a.y += w1.y; a.z += w1.z; a.w += w1.w;
            a.x += w2.x; a.y += w2.y; a.z += w2.z; a.w += w2.w;
            a.x += w3.x; a.y += w3.y; a.z += w3.z; a.w += w3.w;
            w0 = p0; w1 = p1; w2 = p2; w3 = p3;
        }
        a.x += w0.x; a.y += w0.y; a.z += w0.z; a.w += w0.w;
        a.x += w1.x; a.y += w1.y; a.z += w1.z; a.w += w1.w;
        a.x += w2.x; a.y += w2.y; a.z += w2.z; a.w += w2.w;
        a.x += w3.x; a.y += w3.y; a.z += w3.z; a.w += w3.w;
        i = nb * 4;
    }
    for (; i < n; i++) {
        float4 w = ldg4_el(W + L[i] * 256 + c4);
        a.x += w.x; a.y += w.y; a.z += w.z; a.w += w.w;
    }
    return a;
}

// ---------------------------------------------------------------------------
// K2: persistent recurrent kernel.
//  Phase A (after L1 built): warps 0-1 gather w11 (base = I1[t+1]+bh1),
//                            warps 2-3 gather w12 (base = bh2). float4/neuron.
//  Phase B (after L2 built): warps 0-1 gather w22, warps 2-7 output partials.
// All recurrent-path accumulation orders bit-identical to the scalar version.
// ---------------------------------------------------------------------------
__global__ __launch_bounds__(256, 1) void recurrent_kernel(
    const float* __restrict__ b_h1g, const float* __restrict__ b_h2g,
    const float* __restrict__ b_og,
    const float* __restrict__ tau_adp_h1, const float* __restrict__ tau_adp_h2,
    const float* __restrict__ tau_m_h1,  const float* __restrict__ tau_m_h2,
    const float* __restrict__ tau_m_o,
    float* __restrict__ out) {

    const int b    = blockIdx.x;
    const int j    = threadIdx.x;
    const int warp = j >> 5;
    const int lane = j & 31;

    __shared__ alignas(16) int L1[H1N];
    __shared__ alignas(16) int L2[H2N];
    __shared__ unsigned msk1[8], msk2[8];
    __shared__ float    part[6 * DOUT];
    __shared__ float    s11_arr[H1N], s22_arr[H2N], h2p_arr[H2N];

    const float alpha1 = expf(-1.f / tau_m_h1[j]);
    const float ro1    = expf(-1.f / tau_adp_h1[j]);
    const float alpha2 = expf(-1.f / tau_m_h2[j]);
    const float ro2    = expf(-1.f / tau_adp_h2[j]);
    const float bh1    = b_h1g[j];
    const float bh2    = b_h2g[j];

    float mem1 = 0.f, spk1 = 0.f, bb1 = BJ0;
    float mem2 = 0.f, spk2 = 0.f, bb2 = BJ0;

    float alpha_o = 0.f, bo = 0.f, mem_o = 0.f, acc_o = 0.f;
    if (j < DOUT) { alpha_o = expf(-1.f / tau_m_o[j]); bo = b_og[j]; }

    const float* I1row = g_I1 + (size_t)b * T_ * H1N;

    // per-gather-thread constants (warps 0-3): column group + float4 biases
    const int   c4    = (warp < 2) ? (j << 2) : ((j - 64) << 2);
    float4 bh1_4 = make_float4(0.f, 0.f, 0.f, 0.f);
    float4 bh2_4 = make_float4(0.f, 0.f, 0.f, 0.f);
    if (warp < 2)                 bh1_4 = *(const float4*)(b_h1g + c4);
    else if (warp < 4)            bh2_4 = *(const float4*)(b_h2g + c4);

    // init state arrays
    s11_arr[j] = I1row[j] + bh1;   // t=0: no recurrent terms
    s22_arr[j] = 0.f;
    __syncthreads();

    int n1 = 0, n2 = 0;

    for (int t = 0; t < T_; t++) {
        const int tn = (t + 1 < T_) ? (t + 1) : (T_ - 1);

        // ---- layer 1 LIF
        float s11 = s11_arr[j];
        bb1  = ro1 * bb1 + BETA_ * (1.f - ro1) * spk1;
        mem1 = mem1 * alpha1 - bb1 * spk1 + (1.f - alpha1) * s11;
        spk1 = (mem1 - bb1 - BJ0 > 0.f) ? 1.f : 0.f;

        unsigned m1 = __ballot_sync(0xffffffffu, spk1 > 0.5f);
        if (lane == 0) msk1[warp] = m1;
        __syncthreads();                                   // A
        {
            int off = 0, tot = 0;
            #pragma unroll
            for (int w = 0; w < 8; w++) {
                int c = __popc(msk1[w]);
                if (w < warp) off += c;
                tot += c;
            }
            if (spk1 > 0.5f) L1[off + __popc(m1 & ((1u << lane) - 1u))] = j;
            n1 = tot;
        }
        __syncthreads();                                   // B: L1 ready

        // ---- Phase A: float4 gathers over L1_t
        if (warp < 2) {
            float4 i1n = *(const float4*)(I1row + tn * H1N + c4);
            float4 base = make_float4(i1n.x + bh1_4.x, i1n.y + bh1_4.y,
                                      i1n.z + bh1_4.z, i1n.w + bh1_4.w);
            float4 r = gather4(L1, (const int4*)L1, n1, g_Wt_h12h1, c4, base);
            *(float4*)(s11_arr + c4) = r;
        } else if (warp < 4) {
            float4 r = gather4(L1, (const int4*)L1, n1, g_Wt_h12h2, c4, bh2_4);
            *(float4*)(h2p_arr + c4) = r;
        }
        __syncthreads();                                   // C

        // ---- layer 2 LIF
        float h2 = h2p_arr[j] + s22_arr[j];
        bb2  = ro2 * bb2 + BETA_ * (1.f - ro2) * spk2;
        mem2 = mem2 * alpha2 - bb2 * spk2 + (1.f - alpha2) * h2;
        spk2 = (mem2 - bb2 - BJ0 > 0.f) ? 1.f : 0.f;

        unsigned m2 = __ballot_sync(0xffffffffu, spk2 > 0.5f);
        if (lane == 0) msk2[warp] = m2;
        __syncthreads();                                   // D
        {
            int off = 0, tot = 0;
            #pragma unroll
            for (int w = 0; w < 8; w++) {
                int c = __popc(msk2[w]);
                if (w < warp) off += c;
                tot += c;
            }
            if (spk2 > 0.5f) L2[off + __popc(m2 & ((1u << lane) - 1u))] = j;
            n2 = tot;
        }
        __syncthreads();                                   // E: L2 ready

        // ---- Phase B: w22 gather (warps 0-1) + output partials (warps 2-7)
        if (warp < 2) {
            float4 r = gather4(L2, (const int4*)L2, n2, g_Wt_h22h2, c4,
                               make_float4(0.f, 0.f, 0.f, 0.f));
            *(float4*)(s22_arr + c4) = r;
        } else {
            const int w6 = warp - 2;
            if (lane < DOUT) {
                float po = 0.f;
                const int i0 = (n2 * w6) / 6;
                const int i1 = (n2 * (w6 + 1)) / 6;
                int i = i0;
                for (; i + 4 <= i1; i += 4) {
                    float w0 = ldg_el(g_Wt_h2o + L2[i]     * DOUT + lane);
                    float w1 = ldg_el(g_Wt_h2o + L2[i + 1] * DOUT + lane);
                    float w2 = ldg_el(g_Wt_h2o + L2[i + 2] * DOUT + lane);
                    float w3 = ldg_el(g_Wt_h2o + L2[i + 3] * DOUT + lane);
                    po += w0; po += w1; po += w2; po += w3;
                }
                for (; i < i1; i++) po += ldg_el(g_Wt_h2o + L2[i] * DOUT + lane);
                part[w6 * DOUT + lane] = po;
            }
        }
        __syncthreads();                                   // F

        // ---- output neuron + softmax accumulate (warp 0)
        if (warp == 0) {
            float oin = 0.f;
            if (lane < DOUT) {
                oin = bo;
                #pragma unroll
                for (int w = 0; w < 6; w++) oin += part[w * DOUT + lane];
            }
            mem_o = mem_o * alpha_o + (1.f - alpha_o) * oin;
            float vv = (lane < DOUT) ? mem_o : -1e30f;
            float mx = vv;
            #pragma unroll
            for (int s = 16; s > 0; s >>= 1)
                mx = fmaxf(mx, __shfl_xor_sync(0xffffffffu, mx, s));
            float e = (lane < DOUT) ? expf(vv - mx) : 0.f;
            float sm = e;
            #pragma unroll
            for (int s = 16; s > 0; s >>= 1)
                sm += __shfl_xor_sync(0xffffffffu, sm, s);
            if (lane < DOUT) acc_o += e / sm;
        }
    }

    if (j < DOUT) out[b * DOUT + j] = acc_o;
}

// ---------------------------------------------------------------------------
extern "C" void kernel_launch(void* const* d_in, const int* in_sizes, int n_in,
                              void* d_out, int out_size) {
    const float* x          = (const float*)d_in[0];
    const float* w_i2h1     = (const float*)d_in[1];
    const float* w_h12h1    = (const float*)d_in[2];
    const float* w_h12h2    = (const float*)d_in[3];
    const float* w_h22h2    = (const float*)d_in[4];
    const float* w_h2o      = (const float*)d_in[5];
    const float* b_h1       = (const float*)d_in[6];
    const float* b_h2       = (const float*)d_in[7];
    const float* b_o        = (const float*)d_in[8];
    const float* tau_adp_h1 = (const float*)d_in[9];
    const float* tau_adp_h2 = (const float*)d_in[10];
    const float* tau_m_h1   = (const float*)d_in[11];
    const float* tau_m_h2   = (const float*)d_in[12];
    const float* tau_m_o    = (const float*)d_in[13];

    // prefer max L1 (weights reused heavily; smem usage is tiny)
    cudaFuncSetAttribute(recurrent_kernel,
                         cudaFuncAttributePreferredSharedMemoryCarveout, 0);
    cudaFuncSetAttribute(input_proj_kernel,
                         cudaFuncAttributePreferredSharedMemoryCarveout, 0);

    prep_kernel<<<(H1N * DIN + 255) / 256, 256>>>(w_i2h1, w_h12h1, w_h12h2,
                                                  w_h22h2, w_h2o);
    input_proj_kernel<<<B_ * T_, 256>>>(x);
    recurrent_kernel<<<B_, 256>>>(b_h1, b_h2, b_o,
                                  tau_adp_h1, tau_adp_h2,
                                  tau_m_h1, tau_m_h2, tau_m_o,
                                  (float*)d_out);
}

// round 7
// speedup vs baseline: 2.3707x; 2.3707x over previous
#include <cuda_runtime.h>
#include <cstdint>

#define B_    256
#define T_    250
#define DIN   700
#define H1N   256
#define H2N   256
#define DOUT  20
#define BJ0   0.01f
#define BETA_ 1.8f
#define XPAD  704                        // padded per-sample spike-list stride

// ---------------- device globals (no allocations allowed) ------------------
__device__ float          g_I1[B_ * T_ * H1N];      // x @ w_i2h1.T
__device__ float          g_Wt_i2h1[DIN * H1N];     // [d][j]
__device__ float2         g_Wpair[H1N * H1N];       // [k][j] = (w11, w12)
__device__ float          g_Wt22[H2N * H2N];        // [k][j]
__device__ float          g_Wt_h2o[H2N * DOUT];     // [k][o]
__device__ unsigned short g_xlist[B_ * T_ * XPAD];  // per-sample active d's
__device__ int            g_xcnt[B_ * T_];

// ---------------- PTX helpers ----------------------------------------------
__device__ __forceinline__ uint32_t smem_u32(const void* p) {
    uint32_t a;
    asm("{ .reg .u64 t; cvta.to.shared.u64 t, %1; cvt.u32.u64 %0, t; }"
        : "=r"(a) : "l"(p));
    return a;
}
__device__ __forceinline__ uint32_t ctarank() {
    uint32_t r; asm("mov.u32 %0, %%cluster_ctarank;" : "=r"(r)); return r;
}
#define MBAR_INIT(addr, cnt) \
    asm volatile("mbarrier.init.shared.b64 [%0], %1;" :: "r"(addr), "r"(cnt) : "memory")
#define ST_CLUSTER_U32(laddr, rnk, val) \
    asm volatile("{ .reg .b32 ra; mapa.shared::cluster.u32 ra, %0, %1; " \
                 "st.shared::cluster.u32 [ra], %2; }" \
                 :: "r"(laddr), "r"(rnk), "r"(val) : "memory")
#define MBAR_ARRIVE_CLUSTER(laddr, rnk) \
    asm volatile("{ .reg .b32 ra; mapa.shared::cluster.u32 ra, %0, %1; " \
                 "mbarrier.arrive.release.cluster.shared::cluster.b64 _, [ra]; }" \
                 :: "r"(laddr), "r"(rnk) : "memory")
#define MBAR_WAIT_PARITY_CLUSTER(laddr, ph) do {                               \
    uint32_t _done = 0;                                                        \
    while (!_done) {                                                           \
        asm volatile("{ .reg .pred p; "                                        \
            "mbarrier.try_wait.parity.acquire.cluster.shared::cta.b64 p, [%1], %2, 0x989680; " \
            "selp.b32 %0, 1, 0, p; }"                                          \
            : "=r"(_done) : "r"(laddr), "r"(ph) : "memory");                   \
    }                                                                          \
} while (0)
#define CLUSTER_SYNC_() do {                                                   \
    asm volatile("barrier.cluster.arrive.aligned;" ::: "memory");              \
    asm volatile("barrier.cluster.wait.aligned;" ::: "memory");                \
} while (0)

// ---------------------------------------------------------------------------
// K0: weight transposes / interleaving
// ---------------------------------------------------------------------------
__global__ void prep_kernel(const float* __restrict__ wi,
                            const float* __restrict__ w11,
                            const float* __restrict__ w12,
                            const float* __restrict__ w22,
                            const float* __restrict__ wo) {
    int idx = blockIdx.x * blockDim.x + threadIdx.x;
    if (idx < H1N * DIN) {
        int r = idx / DIN, c = idx % DIN;
        g_Wt_i2h1[c * H1N + r] = wi[idx];
    }
    if (idx < H1N * H1N) {
        int r = idx / H1N, c = idx % H1N;
        g_Wpair[c * H1N + r] = make_float2(w11[idx], w12[idx]);
        g_Wt22[c * H1N + r]  = w22[idx];
    }
    if (idx < DOUT * H2N) {
        int r = idx / H2N, c = idx % H2N;
        g_Wt_h2o[c * DOUT + r] = wo[idx];
    }
}

// ---------------------------------------------------------------------------
// K0b: per-sample active-input lists (ascending d), one warp per sample
// ---------------------------------------------------------------------------
__global__ __launch_bounds__(256) void xlist_kernel(const float* __restrict__ x) {
    int s    = blockIdx.x * 8 + (threadIdx.x >> 5);
    int lane = threadIdx.x & 31;
    if (s >= B_ * T_) return;
    const float* xr = x + (size_t)s * DIN;
    int cnt = 0;
    for (int base = 0; base < DIN; base += 32) {
        int d = base + lane;
        float v = (d < DIN) ? xr[d] : 0.f;
        unsigned m = __ballot_sync(0xffffffffu, v != 0.f);
        if (v != 0.f)
            g_xlist[(size_t)s * XPAD + cnt + __popc(m & ((1u << lane) - 1u))] =
                (unsigned short)d;
        cnt += __popc(m);
    }
    if (lane == 0) g_xcnt[s] = cnt;
}

// ---------------------------------------------------------------------------
// K1: input projection, col-split smem weight tile.
// blockIdx.x = col-tile (8 x 32 cols), blockIdx.y = sample group (100 x 640).
// Warp handles one sample at a time: lanes = 32 cols, ascending-d gather
// from smem — bitwise identical per-neuron order to the R1 version.
// ---------------------------------------------------------------------------
__global__ __launch_bounds__(256, 2) void input_proj_kernel() {
    extern __shared__ float wt[];                 // [700][32]
    const int ct   = blockIdx.x;
    const int grp  = blockIdx.y;
    const int tid  = threadIdx.x;
    const int warp = tid >> 5;
    const int lane = tid & 31;

    for (int idx = tid; idx < DIN * 32; idx += 256) {
        int d = idx >> 5, c = idx & 31;
        wt[idx] = g_Wt_i2h1[d * H1N + ct * 32 + c];
    }
    __syncthreads();

    for (int si = 0; si < 80; si++) {
        const int s = grp * 640 + warp * 80 + si;
        const int n = g_xcnt[s];
        const unsigned short* ls = g_xlist + (size_t)s * XPAD;
        float acc = 0.f;
        int i = 0;
        for (; i + 4 <= n; i += 4) {
            ushort4 kk = *(const ushort4*)(ls + i);
            acc += wt[kk.x * 32 + lane];
            acc += wt[kk.y * 32 + lane];
            acc += wt[kk.z * 32 + lane];
            acc += wt[kk.w * 32 + lane];
        }
        for (; i < n; i++) acc += wt[ls[i] * 32 + lane];
        g_I1[(size_t)s * H1N + ct * 32 + lane] = acc;
    }
}

// ---------------------------------------------------------------------------
// K2: cluster-cooperative recurrent kernel.
// Cluster = 8 CTAs; CTA rank r owns cols [32r, 32r+32) of w11/w12/w22 in smem
// and processes 8 batch elements (warp b <-> batch cluster*8+b; thread (b,c)
// owns neuron j = 32r + c of that batch — all LIF state in registers).
// Per step: LIF1 -> ballot -> DSMEM mask exchange -> list build -> smem
// gather (w11 for t+1 merged with w12 for t) -> LIF2 -> exchange -> w22
// gather; rank-0 CTA computes the 20-wide output + softmax per batch.
// Per-neuron summation order identical to the R3 kernel.
// ---------------------------------------------------------------------------
#define SM_WPAIR 0
#define SM_W22   65536
#define SM_L1    98304
#define SM_L2    100352
#define SM_MB1   102400
#define SM_MB2   102912
#define SM_BAR1  103424
#define SM_BAR2  103432
#define SM_TOT   103456

__global__ __launch_bounds__(256, 2) __cluster_dims__(8, 1, 1)
void recurrent_kernel(
    const float* __restrict__ b_h1g, const float* __restrict__ b_h2g,
    const float* __restrict__ b_og,
    const float* __restrict__ tau_adp_h1, const float* __restrict__ tau_adp_h2,
    const float* __restrict__ tau_m_h1,  const float* __restrict__ tau_m_h2,
    const float* __restrict__ tau_m_o,
    float* __restrict__ out) {

    extern __shared__ __align__(16) char smraw[];
    float2*        wpair_s = (float2*)(smraw + SM_WPAIR);   // [k*32+c]
    float*         w22_s   = (float*)(smraw + SM_W22);      // [k*32+c]
    uint8_t*       L1s     = (uint8_t*)(smraw + SM_L1);     // [b][256]
    uint8_t*       L2s     = (uint8_t*)(smraw + SM_L2);
    const uint32_t*mb1     = (const uint32_t*)(smraw + SM_MB1); // [par][src][b]
    const uint32_t*mb2     = (const uint32_t*)(smraw + SM_MB2);
    const uint32_t smb     = smem_u32(smraw);
    const uint32_t bar1    = smb + SM_BAR1;
    const uint32_t bar2    = smb + SM_BAR2;
    const uint32_t mb1a    = smb + SM_MB1;
    const uint32_t mb2a    = smb + SM_MB2;

    const int tid   = threadIdx.x;
    const int b     = tid >> 5;            // warp = local batch
    const int c     = tid & 31;            // lane = local column
    const uint32_t rank = ctarank();
    const int j     = rank * 32 + c;       // owned neuron
    const int gb    = (blockIdx.x >> 3) * 8 + b;   // global batch

    // ---- load weight slices to smem
    for (int idx = tid; idx < H1N * 32; idx += 256) {
        int k = idx >> 5, cc = idx & 31;
        wpair_s[idx] = g_Wpair[k * H1N + rank * 32 + cc];
        w22_s[idx]   = g_Wt22[k * H1N + rank * 32 + cc];
    }
    if (tid == 0) { MBAR_INIT(bar1, 64); MBAR_INIT(bar2, 64); }
    __syncthreads();
    CLUSTER_SYNC_();

    // ---- per-neuron params/state
    const float alpha1 = expf(-1.f / tau_m_h1[j]);
    const float ro1    = expf(-1.f / tau_adp_h1[j]);
    const float alpha2 = expf(-1.f / tau_m_h2[j]);
    const float ro2    = expf(-1.f / tau_adp_h2[j]);
    const float bh1    = b_h1g[j];
    const float bh2    = b_h2g[j];

    float mem1 = 0.f, spk1 = 0.f, bb1 = BJ0;
    float mem2 = 0.f, spk2 = 0.f, bb2 = BJ0;

    float alpha_o = 0.f, bo = 0.f, mem_o = 0.f, acc_o = 0.f;
    if (rank == 0 && c < DOUT) { alpha_o = expf(-1.f / tau_m_o[c]); bo = b_og[c]; }

    const float* I1row = g_I1 + (size_t)gb * T_ * H1N;
    float s11 = I1row[j] + bh1;       // t=0: no recurrent terms
    float s22 = 0.f;

    uint8_t* L1b = L1s + b * 256;
    uint8_t* L2b = L2s + b * 256;

    for (int t = 0; t < T_; t++) {
        const int tn  = (t + 1 < T_) ? (t + 1) : (T_ - 1);
        const int par = t & 1;

        // ---- layer 1 LIF
        bb1  = ro1 * bb1 + BETA_ * (1.f - ro1) * spk1;
        mem1 = mem1 * alpha1 - bb1 * spk1 + (1.f - alpha1) * s11;
        spk1 = (mem1 - bb1 - BJ0 > 0.f) ? 1.f : 0.f;

        unsigned m1 = __ballot_sync(0xffffffffu, spk1 > 0.5f);
        {   // lanes 0-7: send my mask word to peer lane's buffer, arrive there
            uint32_t laddr = mb1a + ((par * 8 + rank) * 8 + b) * 4;
            if (c < 8) { ST_CLUSTER_U32(laddr, (uint32_t)c, m1);
                         MBAR_ARRIVE_CLUSTER(bar1, (uint32_t)c); }
        }
        MBAR_WAIT_PARITY_CLUSTER(bar1, par);

        // ---- build L1 for batch b (ascending neuron index)
        int n1 = 0;
        #pragma unroll
        for (int m = 0; m < 8; m++) {
            unsigned w = mb1[(par * 8 + m) * 8 + b];
            if (w & (1u << c))
                L1b[n1 + __popc(w & ((1u << c) - 1u))] = (uint8_t)(m * 32 + c);
            n1 += __popc(w);
        }
        __syncwarp();

        // ---- merged gather over L1: w11 -> s11(t+1), w12 -> h2 part
        float a1 = I1row[tn * H1N + j] + bh1;
        float a2 = bh2;
        {
            int i = 0;
            for (; i + 4 <= n1; i += 4) {
                unsigned kk = *(const unsigned*)(L1b + i);
                float2 w0 = wpair_s[(kk & 255u) * 32 + c];
                float2 w1 = wpair_s[((kk >> 8) & 255u) * 32 + c];
                float2 w2 = wpair_s[((kk >> 16) & 255u) * 32 + c];
                float2 w3 = wpair_s[(kk >> 24) * 32 + c];
                a1 += w0.x; a2 += w0.y;
                a1 += w1.x; a2 += w1.y;
                a1 += w2.x; a2 += w2.y;
                a1 += w3.x; a2 += w3.y;
            }
            for (; i < n1; i++) {
                float2 w = wpair_s[L1b[i] * 32 + c];
                a1 += w.x; a2 += w.y;
            }
        }
        s11 = a1;

        // ---- layer 2 LIF
        float h2 = a2 + s22;
        bb2  = ro2 * bb2 + BETA_ * (1.f - ro2) * spk2;
        mem2 = mem2 * alpha2 - bb2 * spk2 + (1.f - alpha2) * h2;
        spk2 = (mem2 - bb2 - BJ0 > 0.f) ? 1.f : 0.f;

        unsigned m2 = __ballot_sync(0xffffffffu, spk2 > 0.5f);
        {
            uint32_t laddr = mb2a + ((par * 8 + rank) * 8 + b) * 4;
            if (c < 8) { ST_CLUSTER_U32(laddr, (uint32_t)c, m2);
                         MBAR_ARRIVE_CLUSTER(bar2, (uint32_t)c); }
        }
        MBAR_WAIT_PARITY_CLUSTER(bar2, par);

        int n2 = 0;
        #pragma unroll
        for (int m = 0; m < 8; m++) {
            unsigned w = mb2[(par * 8 + m) * 8 + b];
            if (w & (1u << c))
                L2b[n2 + __popc(w & ((1u << c) - 1u))] = (uint8_t)(m * 32 + c);
            n2 += __popc(w);
        }
        __syncwarp();

        // ---- gather w22 over L2 -> s22(t+1)
        float a3 = 0.f;
        {
            int i = 0;
            for (; i + 4 <= n2; i += 4) {
                unsigned kk = *(const unsigned*)(L2b + i);
                float w0 = w22_s[(kk & 255u) * 32 + c];
                float w1 = w22_s[((kk >> 8) & 255u) * 32 + c];
                float w2 = w22_s[((kk >> 16) & 255u) * 32 + c];
                float w3 = w22_s[(kk >> 24) * 32 + c];
                a3 += w0; a3 += w1; a3 += w2; a3 += w3;
            }
            for (; i < n2; i++) a3 += w22_s[L2b[i] * 32 + c];
        }
        s22 = a3;

        // ---- output + softmax (rank-0 CTA, warp b = batch b)
        if (rank == 0) {
            float oin = 0.f;
            if (c < DOUT) {
                oin = bo;
                int i = 0;
                for (; i + 4 <= n2; i += 4) {
                    unsigned kk = *(const unsigned*)(L2b + i);
                    float w0 = g_Wt_h2o[(kk & 255u) * DOUT + c];
                    float w1 = g_Wt_h2o[((kk >> 8) & 255u) * DOUT + c];
                    float w2 = g_Wt_h2o[((kk >> 16) & 255u) * DOUT + c];
                    float w3 = g_Wt_h2o[(kk >> 24) * DOUT + c];
                    oin += w0; oin += w1; oin += w2; oin += w3;
                }
                for (; i < n2; i++) oin += g_Wt_h2o[L2b[i] * DOUT + c];
            }
            mem_o = mem_o * alpha_o + (1.f - alpha_o) * oin;
            float vv = (c < DOUT) ? mem_o : -1e30f;
            float mx = vv;
            #pragma unroll
            for (int s = 16; s > 0; s >>= 1)
                mx = fmaxf(mx, __shfl_xor_sync(0xffffffffu, mx, s));
            float e = (c < DOUT) ? expf(vv - mx) : 0.f;
            float sm = e;
            #pragma unroll
            for (int s = 16; s > 0; s >>= 1)
                sm += __shfl_xor_sync(0xffffffffu, sm, s);
            if (c < DOUT) acc_o += e / sm;
        }
    }

    if (rank == 0 && c < DOUT) out[gb * DOUT + c] = acc_o;
    CLUSTER_SYNC_();
}

// ---------------------------------------------------------------------------
extern "C" void kernel_launch(void* const* d_in, const int* in_sizes, int n_in,
                              void* d_out, int out_size) {
    const float* x          = (const float*)d_in[0];
    const float* w_i2h1     = (const float*)d_in[1];
    const float* w_h12h1    = (const float*)d_in[2];
    const float* w_h12h2    = (const float*)d_in[3];
    const float* w_h22h2    = (const float*)d_in[4];
    const float* w_h2o      = (const float*)d_in[5];
    const float* b_h1       = (const float*)d_in[6];
    const float* b_h2       = (const float*)d_in[7];
    const float* b_o        = (const float*)d_in[8];
    const float* tau_adp_h1 = (const float*)d_in[9];
    const float* tau_adp_h2 = (const float*)d_in[10];
    const float* tau_m_h1   = (const float*)d_in[11];
    const float* tau_m_h2   = (const float*)d_in[12];
    const float* tau_m_o    = (const float*)d_in[13];

    cudaFuncSetAttribute(input_proj_kernel,
                         cudaFuncAttributeMaxDynamicSharedMemorySize, DIN * 32 * 4);
    cudaFuncSetAttribute(recurrent_kernel,
                         cudaFuncAttributeMaxDynamicSharedMemorySize, SM_TOT);

    prep_kernel<<<(H1N * DIN + 255) / 256, 256>>>(w_i2h1, w_h12h1, w_h12h2,
                                                  w_h22h2, w_h2o);
    xlist_kernel<<<(B_ * T_) / 8, 256>>>(x);
    input_proj_kernel<<<dim3(8, 100), 256, DIN * 32 * 4>>>();
    recurrent_kernel<<<B_, 256, SM_TOT>>>(b_h1, b_h2, b_o,
                                          tau_adp_h1, tau_adp_h2,
                                          tau_m_h1, tau_m_h2, tau_m_o,
                                          (float*)d_out);
}